// round 4
// baseline (speedup 1.0000x reference)
#include <cuda_runtime.h>
#include <math.h>

#define B_ 32
#define L_ 256
#define A_ 20
#define TILE_F 640          // floats per transposed+swizzled tile (20 x 32)
#define NTHR 640
#define STILE 16            // tiles per stage
#define NSTAGE 16

// Per-i results: {lse_sum, pair_sum, reg_sum}
__device__ double g_res[L_][3];
__device__ unsigned int g_bcount = 0;   // reset by last block each launch

// Dynamic smem layout (bytes):
//   [0     , 40960)  buf: 16 tiles x 640 floats
//   [40960 , 49152)  xch8: x as bytes [32][256]
//   [49152 , 49280)  xi[32] (int)
//   [49280 , 49360)  wsrow[20]
//   [49360 , 49440)  csts[20]
//   [49440 , 49520)  sredr[20]
//   [49520 , 49524)  amLast flag
#define SMEM_BYTES 49524

__global__ __launch_bounds__(NTHR, 2) void mrf_kernelA(const int* __restrict__ x,
                                                       const float* __restrict__ ws,
                                                       const float* __restrict__ wp,
                                                       float* __restrict__ out) {
    extern __shared__ char smem_raw[];
    float*         buf   = reinterpret_cast<float*>(smem_raw);
    unsigned char* xch8  = reinterpret_cast<unsigned char*>(smem_raw + 40960);
    int*           xi    = reinterpret_cast<int*>(smem_raw + 49152);
    float*         wsrow = reinterpret_cast<float*>(smem_raw + 49280);
    float*         csts  = reinterpret_cast<float*>(smem_raw + 49360);
    float*         sredr = reinterpret_cast<float*>(smem_raw + 49440);
    int*           amLast= reinterpret_cast<int*>(smem_raw + 49520);

    const int i    = blockIdx.x;
    const int tid  = threadIdx.x;
    const int wid  = tid >> 5;
    const int lane = tid & 31;

    // thread -> (tsub, b, jg): tid = tsub*160 + b*5 + jg; tsub owns 4 tiles/stage
    const int tsub = tid / 160;
    const int rr   = tid - tsub * 160;
    const int b    = rr / 5;
    const int jg   = rr - b * 5;
    const int tb   = tsub * 4 * TILE_F;

    // Stage-0 prefetch first (float2 granularity: 3200 float2 per stage).
    const float2* wp2 = reinterpret_cast<const float2*>(wp);
    const size_t base2 = (size_t)i * 51200;      // 256 tiles * 200 float2
    float2 v[5];
#pragma unroll
    for (int w = 0; w < 5; w++) v[w] = wp2[base2 + tid + w * NTHR];

    // Prologue fills.
    for (int n = tid; n < B_ * L_; n += NTHR) xch8[n] = (unsigned char)x[n];
    if (tid < B_) xi[tid] = x[tid * L_ + i];
    if (tid >= 32 && tid < 52) wsrow[tid - 32] = ws[i * A_ + (tid - 32)];

    // Stage-invariant swizzled store offsets (float2 -> 2 STS.32, +0 and +32).
    int dstb[5];
#pragma unroll
    for (int w = 0; w < 5; w++) {
        int slot = tid + w * NTHR;      // float2 slot 0..3199
        int f  = slot * 2;              // element within stage
        int t  = f / 400;
        int r  = f - t * 400;
        int j  = r / 20;
        int e0 = r - j * 20;            // even, and e0+1 stays in same quad
        dstb[w] = t * TILE_F + (e0 << 5) + ((((j >> 2) ^ (e0 >> 2)) & 7) << 2) + (j & 3);
    }

    float a0 = 0.f, a1 = 0.f, a2 = 0.f, a3 = 0.f;
    float reg_acc = 0.f, pair_acc = 0.f, c_acc = 0.f;

    __syncthreads();
    int xihi = 0, xilo = 0;
    if (wid == 18) { int e = xi[lane]; xihi = e >> 2; xilo = e & 3; }
    const int jc   = tid - 608;  // const-warp j (warp 19, lanes 0..19)
    const int co19 = 608 + ((((jc >> 2) ^ 4) & 7) << 2) + (jc & 3);

    for (int s = 0; s < NSTAGE; s++) {
#pragma unroll
        for (int w = 0; w < 5; w++) {
            float2 q = v[w];
            reg_acc += fmaf(q.x, q.x, fabsf(q.x));
            reg_acc += fmaf(q.y, q.y, fabsf(q.y));
            buf[dstb[w]     ] = q.x;
            buf[dstb[w] + 32] = q.y;
        }
        __syncthreads();

        if (s < NSTAGE - 1) {
            size_t nb = base2 + (size_t)(s + 1) * 3200;
#pragma unroll
            for (int w = 0; w < 5; w++) v[w] = wp2[nb + tid + w * NTHR];
        }

        // Main gather: 4 tiles/thread, 4 j's per LDS.128.
        {
            const unsigned int xw = *reinterpret_cast<const unsigned int*>(
                xch8 + b * L_ + (s << 4) + (tsub << 2));
            const int pbase = (s << 4) + (tsub << 2);
#pragma unroll
            for (int k = 0; k < 4; k++) {
                int e = (xw >> (k * 8)) & 0xff;
                if (pbase + k > i) {
                    const float4 g = *reinterpret_cast<const float4*>(
                        &buf[tb + k * TILE_F + (e << 5) + (((jg ^ (e >> 2)) & 7) << 2)]);
                    a0 += g.x; a1 += g.y; a2 += g.z; a3 += g.w;
                }
            }
        }

        // Pair energy: warp 18, lane = b2, 16 tiles.
        if (wid == 18) {
            const uint4 w0 = *reinterpret_cast<const uint4*>(xch8 + lane * L_ + (s << 4));
            unsigned int wv[4] = {w0.x, w0.y, w0.z, w0.w};
#pragma unroll
            for (int t = 0; t < STILE; t++) {
                int e = (wv[t >> 2] >> ((t & 3) * 8)) & 0xff;
                pair_acc += buf[t * TILE_F + (e << 5) + (((xihi ^ (e >> 2)) & 7) << 2) + xilo];
            }
        }

        // Const terms: warp 19 lanes 0..19.  p<i: M[j][19];  p==i: M[j][j].
        if (jc >= 0 && jc < 20) {
            int tmax = i - (s << 4);
            int lim = tmax < STILE ? tmax : STILE;
            for (int t = 0; t < lim; t++) c_acc += buf[t * TILE_F + co19];
            if (tmax >= 0 && tmax < STILE)
                c_acc += buf[tmax * TILE_F + (jc << 5) + (jc & 3)];
        }
        __syncthreads();
    }

    // ---- Epilogue (buf reused for partials) ----
    *reinterpret_cast<float4*>(&buf[tsub * 640 + b * A_ + (jg << 2)]) =
        make_float4(a0, a1, a2, a3);
    if (jc >= 0 && jc < 20) csts[jc] = c_acc;

    float rv = reg_acc;
#pragma unroll
    for (int o = 16; o > 0; o >>= 1) rv += __shfl_down_sync(0xffffffffu, rv, o);
    if (lane == 0) sredr[wid] = rv;

    if (wid == 18) {
        float pv = pair_acc;
#pragma unroll
        for (int o = 16; o > 0; o >>= 1) pv += __shfl_down_sync(0xffffffffu, pv, o);
        if (lane == 0) g_res[i][1] = (double)pv;
    }
    __syncthreads();

    {   // combine tsub partials + const + ws
        const int j = tid - (tid / A_) * A_;
        buf[tid] = buf[tid] + buf[640 + tid] + buf[1280 + tid] + buf[1920 + tid]
                 + csts[j] + wsrow[j];
        if (tid == 0) {
            double rs = 0.0;
            for (int w = 0; w < 20; w++) rs += (double)sredr[w];
            g_res[i][2] = rs;
        }
    }
    __syncthreads();

    if (tid < 32) {   // lse per b, minus single
        const float* row = &buf[tid * A_];
        float m = row[0];
#pragma unroll
        for (int j = 1; j < A_; j++) m = fmaxf(m, row[j]);
        float se = 0.f;
#pragma unroll
        for (int j = 0; j < A_; j++) se += __expf(row[j] - m);
        float lse = m + __logf(se);
        double val = (double)lse - (double)wsrow[xi[tid]];
#pragma unroll
        for (int o = 16; o > 0; o >>= 1) val += __shfl_down_sync(0xffffffffu, val, o);
        if (tid == 0) g_res[i][0] = val;
    }
    __syncthreads();

    // ---- Fused deterministic final reduction (last CTA) ----
    if (tid == 0) {
        __threadfence();
        *amLast = (atomicAdd(&g_bcount, 1u) == gridDim.x - 1u) ? 1 : 0;
    }
    __syncthreads();
    if (!*amLast) return;
    __threadfence();

    double LS = 0.0, PA = 0.0, RP = 0.0, RS = 0.0;
    if (tid < L_) { LS = g_res[tid][0]; PA = g_res[tid][1]; RP = g_res[tid][2]; }
    for (int n = tid; n < L_ * A_; n += NTHR) {
        float w = ws[n];
        RS += (double)fabsf(w) + (double)w * (double)w;
    }
    double* dred = reinterpret_cast<double*>(smem_raw);   // buf reused as doubles
#pragma unroll
    for (int o = 16; o > 0; o >>= 1) {
        LS += __shfl_down_sync(0xffffffffu, LS, o);
        PA += __shfl_down_sync(0xffffffffu, PA, o);
        RP += __shfl_down_sync(0xffffffffu, RP, o);
        RS += __shfl_down_sync(0xffffffffu, RS, o);
    }
    if (lane == 0) {
        dred[wid] = LS; dred[32 + wid] = PA; dred[64 + wid] = RP; dred[96 + wid] = RS;
    }
    __syncthreads();
    if (tid == 0) {
        double ls = 0, pa = 0, rp = 0, rs = 0;
        for (int w = 0; w < 20; w++) {
            ls += dred[w]; pa += dred[32 + w]; rp += dred[64 + w]; rs += dred[96 + w];
        }
        // LAMBDA_SINGLE = 1.0, LAMBDA_PAIR = 0.2*(L-1) = 51.0
        out[0] = (float)((ls - pa) / (double)B_ + 1.0 * rs + 51.0 * rp);
        g_bcount = 0;   // self-reset for graph replay
    }
}

extern "C" void kernel_launch(void* const* d_in, const int* in_sizes, int n_in,
                              void* d_out, int out_size) {
    (void)in_sizes; (void)n_in; (void)out_size;
    const int*   x  = (const int*)d_in[0];
    const float* ws = (const float*)d_in[1];
    const float* wp = (const float*)d_in[2];
    float* out = (float*)d_out;

    cudaFuncSetAttribute(mrf_kernelA, cudaFuncAttributeMaxDynamicSharedMemorySize, SMEM_BYTES);
    mrf_kernelA<<<L_, NTHR, SMEM_BYTES>>>(x, ws, wp, out);
}

// round 5
// speedup vs baseline: 1.1461x; 1.1461x over previous
#include <cuda_runtime.h>
#include <math.h>
#include <stdint.h>

#define B_ 32
#define L_ 256
#define A_ 20
#define NTHR 672            // 20 consumer warps + 1 producer warp
#define NCONS 640
#define TS 8                // tiles per stage
#define RING 4
#define NSTAGE 32           // 256 tiles / 8
#define STAGE_F 3200        // floats per stage
#define STAGE_BYTES 12800

__device__ double g_res[L_][3];          // per-i {lse_sum, pair_sum, reg_sum}
__device__ unsigned int g_bcount = 0;    // reset by last block each launch

// smem layout (bytes):
//   0     .. 51200  ring data (4 x 12800), row-major tiles
//   51200 .. 59392  xpk (2048 uint32): bytes x[b][4*p4..4*p4+3] at [p4*32+b]
//   59392 .. 59520  xi[32]
//   59520 .. 59600  wsrow[20]
//   59600 .. 59684  sredr[21]
//   59696 .. 59824  mbarriers: per r (stride 16): full at +0, empty at +8
//   59824 .. 59828  amLast
// epilogue reuse of ring region: lgbuf f32[32*21] @f0, pairv f32[32] @f800,
//   dred double[4*32] @byte 4096
#define SMEM_BYTES 59840
#define MB_OFF 59696

__device__ __forceinline__ uint32_t smem_u32(const void* p) {
    uint32_t a;
    asm("{ .reg .u64 t; cvta.to.shared.u64 t, %1; cvt.u32.u64 %0, t; }" : "=r"(a) : "l"(p));
    return a;
}
#define MB_INIT(addr, cnt) \
    asm volatile("mbarrier.init.shared.b64 [%0], %1;" :: "r"(addr), "r"(cnt) : "memory")
#define MB_EXPECT_TX(addr, bytes) \
    asm volatile("mbarrier.arrive.expect_tx.shared.b64 _, [%0], %1;" :: "r"(addr), "r"(bytes) : "memory")
#define MB_ARRIVE(addr) \
    asm volatile("mbarrier.arrive.shared.b64 _, [%0];" :: "r"(addr) : "memory")

__device__ __forceinline__ void mb_wait_acq(uint32_t mbar, uint32_t parity) {
    asm volatile(
        "{\n\t.reg .pred P;\n\t"
        "WL_%=:\n\t"
        "mbarrier.try_wait.parity.acquire.cta.shared::cta.b64 P, [%0], %1, 0x989680;\n\t"
        "@P bra.uni WD_%=;\n\t"
        "bra.uni WL_%=;\n\t"
        "WD_%=:\n\t}"
        :: "r"(mbar), "r"(parity) : "memory");
}
__device__ __forceinline__ void mb_wait_rlx(uint32_t mbar, uint32_t parity) {
    asm volatile(
        "{\n\t.reg .pred P;\n\t"
        "WL_%=:\n\t"
        "mbarrier.try_wait.parity.relaxed.cta.shared::cta.b64 P, [%0], %1, 0x989680;\n\t"
        "@P bra.uni WD_%=;\n\t"
        "bra.uni WL_%=;\n\t"
        "WD_%=:\n\t}"
        :: "r"(mbar), "r"(parity) : "memory");
}
__device__ __forceinline__ void bulk_g2s(uint32_t dst, const void* src,
                                         uint32_t bytes, uint32_t mbar) {
    asm volatile(
        "cp.async.bulk.shared::cta.global.mbarrier::complete_tx::bytes [%0], [%1], %2, [%3];"
        :: "r"(dst), "l"(src), "r"(bytes), "r"(mbar) : "memory");
}

__global__ __launch_bounds__(NTHR, 2) void mrf_kernel(const int* __restrict__ x,
                                                      const float* __restrict__ ws,
                                                      const float* __restrict__ wp,
                                                      float* __restrict__ out) {
    extern __shared__ char smem_raw[];
    float*        bufs  = reinterpret_cast<float*>(smem_raw);
    uint32_t*     xpk   = reinterpret_cast<uint32_t*>(smem_raw + 51200);
    int*          xi    = reinterpret_cast<int*>(smem_raw + 59392);
    float*        wsrow = reinterpret_cast<float*>(smem_raw + 59520);
    float*        sredr = reinterpret_cast<float*>(smem_raw + 59600);
    int*          amLast= reinterpret_cast<int*>(smem_raw + 59824);
    const uint32_t mb0  = smem_u32(smem_raw + MB_OFF);
    const uint32_t bufa = smem_u32(smem_raw);

    const int i    = blockIdx.x;
    const int tid  = threadIdx.x;
    const int wid  = tid >> 5;
    const int lane = tid & 31;

    // mbarrier init: full count=1 (tx-based), empty count=20 (one arrive/consumer warp)
    if (tid == 0) {
        for (int r = 0; r < RING; r++) {
            MB_INIT(mb0 + r * 16, 1);
            MB_INIT(mb0 + r * 16 + 8, 20);
        }
    }

    // Pack x transpose: xpk[p4*32+b] = bytes x[b][4p4..4p4+3]
    const int4* x4 = reinterpret_cast<const int4*>(x);
    for (int n = tid; n < 2048; n += NTHR) {
        int p4 = n >> 5, b = n & 31;
        int4 q = x4[b * 64 + p4];
        xpk[n] = (uint32_t)(q.x & 0xff) | ((uint32_t)(q.y & 0xff) << 8) |
                 ((uint32_t)(q.z & 0xff) << 16) | ((uint32_t)(q.w & 0xff) << 24);
    }
    if (tid < B_) xi[tid] = x[tid * L_ + i];
    if (tid >= 32 && tid < 52) wsrow[tid - 32] = ws[i * A_ + (tid - 32)];
    asm volatile("fence.proxy.async.shared::cta;" ::: "memory");
    __syncthreads();

    float acc = 0.f, pair = 0.f, c_acc = 0.f, reg = 0.f;
    bool flag = false;
    if (wid < 20) flag = (wid == xi[lane]);

    if (tid == NCONS) {
        // ---------------- Producer (single thread) ----------------
        const char* src = reinterpret_cast<const char*>(wp) + (size_t)i * 409600;
        for (int sidx = 0; sidx < NSTAGE; sidx++) {
            int r = sidx & 3;
            if (sidx >= RING) mb_wait_rlx(mb0 + r * 16 + 8, ((sidx >> 2) & 1) ^ 1);
            MB_EXPECT_TX(mb0 + r * 16, STAGE_BYTES);
            bulk_g2s(bufa + r * STAGE_BYTES, src + (size_t)sidx * STAGE_BYTES,
                     STAGE_BYTES, mb0 + r * 16);
        }
    } else if (tid < NCONS) {
        // ---------------- Consumers: warp = j, lane = b ----------------
        const int j20 = wid * 20;
        for (int sidx = 0; sidx < NSTAGE; sidx++) {
            const int r = sidx & 3;
            mb_wait_acq(mb0 + r * 16, (sidx >> 2) & 1);
            const float* bt = bufs + r * STAGE_F;
            const int pbase = sidx * TS;
            const uint32_t u0 = xpk[sidx * 64 + lane];
            const uint32_t u1 = xpk[sidx * 64 + 32 + lane];

            // reg pass: |w| + w^2 over this stage (conflict-free strided)
#pragma unroll
            for (int w = 0; w < 5; w++) {
                float q = bt[tid + w * NCONS];
                reg += fmaf(q, q, fabsf(q));
            }

            if (pbase > i) {
                // ABOVE: all p > i
#pragma unroll
                for (int k = 0; k < TS; k++) {
                    int e = ((k < 4 ? u0 : u1) >> ((k & 3) * 8)) & 0xff;
                    float v = bt[k * 400 + j20 + e];
                    acc += v;
                    if (flag) pair += v;
                }
            } else if (pbase + TS - 1 < i) {
                // BELOW: all p < i — only pair (flagged) + const (lane 0)
                if (flag) {
#pragma unroll
                    for (int k = 0; k < TS; k++) {
                        int e = ((k < 4 ? u0 : u1) >> ((k & 3) * 8)) & 0xff;
                        pair += bt[k * 400 + j20 + e];
                    }
                }
                if (lane == 0) {
#pragma unroll
                    for (int k = 0; k < TS; k++) c_acc += bt[k * 400 + j20 + 19];
                }
            } else {
                // MIXED: straddles i
#pragma unroll
                for (int k = 0; k < TS; k++) {
                    int e = ((k < 4 ? u0 : u1) >> ((k & 3) * 8)) & 0xff;
                    float v = bt[k * 400 + j20 + e];
                    int p = pbase + k;
                    if (p > i) acc += v;
                    if (flag) pair += v;
                    if (lane == 0) {
                        if (p < i)  c_acc += bt[k * 400 + j20 + 19];
                        if (p == i) c_acc += bt[k * 400 + j20 + wid];
                    }
                }
            }
            if (lane == 0) MB_ARRIVE(mb0 + r * 16 + 8);
        }
    }

    // ---------------- Epilogue ----------------
    __syncthreads();
    if (wid < 20) {
        float cbc = __shfl_sync(0xffffffffu, c_acc, 0);
        bufs[lane * 21 + wid] = acc + cbc + wsrow[wid];   // lgbuf[b*21+j]
        if (flag) bufs[800 + lane] = pair;                 // pairv[b]
        float rv = reg;
#pragma unroll
        for (int o = 16; o > 0; o >>= 1) rv += __shfl_down_sync(0xffffffffu, rv, o);
        if (lane == 0) sredr[wid] = rv;
    }
    __syncthreads();

    if (tid < 32) {
        const float* row = &bufs[tid * 21];
        float m = row[0];
#pragma unroll
        for (int j = 1; j < A_; j++) m = fmaxf(m, row[j]);
        float se = 0.f;
#pragma unroll
        for (int j = 0; j < A_; j++) se += __expf(row[j] - m);
        float lse = m + __logf(se);
        double val = (double)lse - (double)wsrow[xi[tid]];
#pragma unroll
        for (int o = 16; o > 0; o >>= 1) val += __shfl_down_sync(0xffffffffu, val, o);
        if (tid == 0) g_res[i][0] = val;
    } else if (tid < 64) {
        double pv = (double)bufs[800 + lane];
#pragma unroll
        for (int o = 16; o > 0; o >>= 1) pv += __shfl_down_sync(0xffffffffu, pv, o);
        if (lane == 0) g_res[i][1] = pv;
    } else if (tid < 96) {
        double rv = (lane < 20) ? (double)sredr[lane] : 0.0;
#pragma unroll
        for (int o = 16; o > 0; o >>= 1) rv += __shfl_down_sync(0xffffffffu, rv, o);
        if (lane == 0) g_res[i][2] = rv;
    }
    __syncthreads();

    // ---------------- Fused deterministic final reduction (last CTA) ----------------
    if (tid == 0) {
        __threadfence();
        *amLast = (atomicAdd(&g_bcount, 1u) == (unsigned)(gridDim.x - 1)) ? 1 : 0;
    }
    __syncthreads();
    if (!*amLast) return;
    __threadfence();

    double LS = 0.0, PA = 0.0, RP = 0.0, RS = 0.0;
    if (tid < L_) { LS = g_res[tid][0]; PA = g_res[tid][1]; RP = g_res[tid][2]; }
    for (int n = tid; n < L_ * A_; n += NTHR) {
        float w = ws[n];
        RS += (double)fabsf(w) + (double)w * (double)w;
    }
    double* dred = reinterpret_cast<double*>(smem_raw + 4096);
#pragma unroll
    for (int o = 16; o > 0; o >>= 1) {
        LS += __shfl_down_sync(0xffffffffu, LS, o);
        PA += __shfl_down_sync(0xffffffffu, PA, o);
        RP += __shfl_down_sync(0xffffffffu, RP, o);
        RS += __shfl_down_sync(0xffffffffu, RS, o);
    }
    if (lane == 0) {
        dred[wid] = LS; dred[32 + wid] = PA; dred[64 + wid] = RP; dred[96 + wid] = RS;
    }
    __syncthreads();
    if (tid == 0) {
        double ls = 0, pa = 0, rp = 0, rs = 0;
        for (int w = 0; w < 21; w++) {
            ls += dred[w]; pa += dred[32 + w]; rp += dred[64 + w]; rs += dred[96 + w];
        }
        // LAMBDA_SINGLE = 1.0, LAMBDA_PAIR = 0.2*(L-1) = 51.0
        out[0] = (float)((ls - pa) / (double)B_ + 1.0 * rs + 51.0 * rp);
        g_bcount = 0;   // self-reset for graph replay
    }
}

extern "C" void kernel_launch(void* const* d_in, const int* in_sizes, int n_in,
                              void* d_out, int out_size) {
    (void)in_sizes; (void)n_in; (void)out_size;
    const int*   x  = (const int*)d_in[0];
    const float* ws = (const float*)d_in[1];
    const float* wp = (const float*)d_in[2];
    float* out = (float*)d_out;

    cudaFuncSetAttribute(mrf_kernel, cudaFuncAttributeMaxDynamicSharedMemorySize, SMEM_BYTES);
    mrf_kernel<<<L_, NTHR, SMEM_BYTES>>>(x, ws, wp, out);
}

// round 6
// speedup vs baseline: 1.2515x; 1.0920x over previous
#include <cuda_runtime.h>
#include <math.h>
#include <stdint.h>

#define B_ 32
#define L_ 256
#define A_ 20
#define NTHR 736            // 20 consumer warps + producer + pair + const warps
#define NCONS 640
#define TS 8                // tiles per stage
#define RING 4
#define NSTAGE 32           // 256 tiles / 8
#define STAGE_F 3200        // floats per stage
#define STAGE_BYTES 12800

__device__ double g_res[L_][3];          // per-i {lse_sum, pair_sum, reg_sum}
__device__ unsigned int g_bcount = 0;    // reset by last block each launch

// smem layout (bytes):
//   0     .. 51200  ring data (4 x 12800), row-major tiles
//   51200 .. 59392  xpk (2048 uint32): bytes x[b][4*p4..4*p4+3] at [p4*32+b]
//   59392 .. 59520  xi[32]
//   59520 .. 59600  wsrow[20]
//   59600 .. 59680  csts[20]
//   59680 .. 59760  sredr[20]
//   59760 .. 59888  mbarriers: per r (stride 16): full at +0, empty at +8
//   59888 .. 59892  amLast
// epilogue reuse of ring region: lgbuf f32[32*21] @f0, dred double[4*32] @byte 4096
#define SMEM_BYTES 59904
#define MB_OFF 59760

__device__ __forceinline__ uint32_t smem_u32(const void* p) {
    uint32_t a;
    asm("{ .reg .u64 t; cvta.to.shared.u64 t, %1; cvt.u32.u64 %0, t; }" : "=r"(a) : "l"(p));
    return a;
}
#define MB_INIT(addr, cnt) \
    asm volatile("mbarrier.init.shared.b64 [%0], %1;" :: "r"(addr), "r"(cnt) : "memory")
#define MB_EXPECT_TX(addr, bytes) \
    asm volatile("mbarrier.arrive.expect_tx.shared.b64 _, [%0], %1;" :: "r"(addr), "r"(bytes) : "memory")
#define MB_ARRIVE(addr) \
    asm volatile("mbarrier.arrive.shared.b64 _, [%0];" :: "r"(addr) : "memory")

__device__ __forceinline__ void mb_wait_acq(uint32_t mbar, uint32_t parity) {
    asm volatile(
        "{\n\t.reg .pred P;\n\t"
        "WL_%=:\n\t"
        "mbarrier.try_wait.parity.acquire.cta.shared::cta.b64 P, [%0], %1, 0x989680;\n\t"
        "@P bra.uni WD_%=;\n\t"
        "bra.uni WL_%=;\n\t"
        "WD_%=:\n\t}"
        :: "r"(mbar), "r"(parity) : "memory");
}
__device__ __forceinline__ void mb_wait_rlx(uint32_t mbar, uint32_t parity) {
    asm volatile(
        "{\n\t.reg .pred P;\n\t"
        "WL_%=:\n\t"
        "mbarrier.try_wait.parity.relaxed.cta.shared::cta.b64 P, [%0], %1, 0x989680;\n\t"
        "@P bra.uni WD_%=;\n\t"
        "bra.uni WL_%=;\n\t"
        "WD_%=:\n\t}"
        :: "r"(mbar), "r"(parity) : "memory");
}
__device__ __forceinline__ void bulk_g2s(uint32_t dst, const void* src,
                                         uint32_t bytes, uint32_t mbar) {
    asm volatile(
        "cp.async.bulk.shared::cta.global.mbarrier::complete_tx::bytes [%0], [%1], %2, [%3];"
        :: "r"(dst), "l"(src), "r"(bytes), "r"(mbar) : "memory");
}

__global__ __launch_bounds__(NTHR, 2) void mrf_kernel(const int* __restrict__ x,
                                                      const float* __restrict__ ws,
                                                      const float* __restrict__ wp,
                                                      float* __restrict__ out) {
    extern __shared__ char smem_raw[];
    float*        bufs  = reinterpret_cast<float*>(smem_raw);
    uint32_t*     xpk   = reinterpret_cast<uint32_t*>(smem_raw + 51200);
    int*          xi    = reinterpret_cast<int*>(smem_raw + 59392);
    float*        wsrow = reinterpret_cast<float*>(smem_raw + 59520);
    float*        csts  = reinterpret_cast<float*>(smem_raw + 59600);
    float*        sredr = reinterpret_cast<float*>(smem_raw + 59680);
    int*          amLast= reinterpret_cast<int*>(smem_raw + 59888);
    const uint32_t mb0  = smem_u32(smem_raw + MB_OFF);
    const uint32_t bufa = smem_u32(smem_raw);

    const int i    = blockIdx.x;
    const int tid  = threadIdx.x;
    const int wid  = tid >> 5;
    const int lane = tid & 31;

    // full: tx-based (count 1). empty: 22 arrivals (20 consumers + pair + const).
    if (tid == 0) {
        for (int r = 0; r < RING; r++) {
            MB_INIT(mb0 + r * 16, 1);
            MB_INIT(mb0 + r * 16 + 8, 22);
        }
    }

    // Pack x transpose: xpk[p4*32+b] = bytes x[b][4p4..4p4+3]
    const int4* x4 = reinterpret_cast<const int4*>(x);
    for (int n = tid; n < 2048; n += NTHR) {
        int p4 = n >> 5, b = n & 31;
        int4 q = x4[b * 64 + p4];
        xpk[n] = (uint32_t)(q.x & 0xff) | ((uint32_t)(q.y & 0xff) << 8) |
                 ((uint32_t)(q.z & 0xff) << 16) | ((uint32_t)(q.w & 0xff) << 24);
    }
    if (tid < B_) xi[tid] = x[tid * L_ + i];
    if (tid >= 32 && tid < 52) wsrow[tid - 32] = ws[i * A_ + (tid - 32)];
    asm volatile("fence.proxy.async.shared::cta;" ::: "memory");
    __syncthreads();

    float acc = 0.f, pair = 0.f, c_acc = 0.f, reg1 = 0.f, reg2 = 0.f;

    if (wid < 20) {
        // ------------- Consumers: warp = j, lane = b; gather p>i + reg pass -------------
        const int j20 = wid * 20;
        const float4* bufs4 = reinterpret_cast<const float4*>(smem_raw);
        for (int sidx = 0; sidx < NSTAGE; sidx++) {
            const int r = sidx & 3;
            mb_wait_acq(mb0 + r * 16, (sidx >> 2) & 1);

            // reg pass: 1 float4 + 1 scalar (covers 3200 floats/stage over 640 lanes)
            {
                float4 q = bufs4[r * 800 + tid];
                float  t = bufs[r * STAGE_F + 2560 + tid];
                reg1 += fabsf(q.x); reg2 = fmaf(q.x, q.x, reg2);
                reg1 += fabsf(q.y); reg2 = fmaf(q.y, q.y, reg2);
                reg1 += fabsf(q.z); reg2 = fmaf(q.z, q.z, reg2);
                reg1 += fabsf(q.w); reg2 = fmaf(q.w, q.w, reg2);
                reg1 += fabsf(t);   reg2 = fmaf(t, t, reg2);
            }

            const int pbase = sidx * TS;
            if (pbase + TS - 1 > i) {     // stage has some p > i
                const float* btj = bufs + r * STAGE_F + j20;
                const uint32_t u0 = xpk[sidx * 64 + lane];
                const uint32_t u1 = xpk[sidx * 64 + 32 + lane];
                if (pbase > i) {          // ABOVE: all 8 tiles
#pragma unroll
                    for (int k = 0; k < TS; k++) {
                        int e = ((k < 4 ? u0 : u1) >> ((k & 3) * 8)) & 0xff;
                        acc += btj[k * 400 + e];
                    }
                } else {                  // MIXED
#pragma unroll
                    for (int k = 0; k < TS; k++) {
                        int e = ((k < 4 ? u0 : u1) >> ((k & 3) * 8)) & 0xff;
                        if (pbase + k > i) acc += btj[k * 400 + e];
                    }
                }
            }
            if (lane == 0) MB_ARRIVE(mb0 + r * 16 + 8);
        }
    } else if (wid == 20) {
        // ------------- Producer (lane 0) -------------
        if (lane == 0) {
            const char* src = reinterpret_cast<const char*>(wp) + (size_t)i * 409600;
            for (int sidx = 0; sidx < NSTAGE; sidx++) {
                int r = sidx & 3;
                if (sidx >= RING) mb_wait_rlx(mb0 + r * 16 + 8, ((sidx >> 2) & 1) ^ 1);
                MB_EXPECT_TX(mb0 + r * 16, STAGE_BYTES);
                bulk_g2s(bufa + r * STAGE_BYTES, src + (size_t)sidx * STAGE_BYTES,
                         STAGE_BYTES, mb0 + r * 16);
            }
        }
    } else if (wid == 21) {
        // ------------- Pair warp: lane = b, all p -------------
        const int xi20 = xi[lane] * 20;
        for (int sidx = 0; sidx < NSTAGE; sidx++) {
            const int r = sidx & 3;
            mb_wait_acq(mb0 + r * 16, (sidx >> 2) & 1);
            const float* bt = bufs + r * STAGE_F + xi20;
            const uint32_t u0 = xpk[sidx * 64 + lane];
            const uint32_t u1 = xpk[sidx * 64 + 32 + lane];
#pragma unroll
            for (int k = 0; k < TS; k++) {
                int e = ((k < 4 ? u0 : u1) >> ((k & 3) * 8)) & 0xff;
                pair += bt[k * 400 + e];
            }
            if (lane == 0) MB_ARRIVE(mb0 + r * 16 + 8);
        }
    } else {
        // ------------- Const warp: lanes 0..19, j = lane -------------
        const int j20 = lane * 20;
        for (int sidx = 0; sidx < NSTAGE; sidx++) {
            const int r = sidx & 3;
            mb_wait_acq(mb0 + r * 16, (sidx >> 2) & 1);
            const int pbase = sidx * TS;
            if (lane < 20 && pbase <= i) {
                const float* bt = bufs + r * STAGE_F;
                int tmax = i - pbase;              // t < tmax  <=>  p < i
                int lim = tmax < TS ? tmax : TS;
                for (int t = 0; t < lim; t++) c_acc += bt[t * 400 + j20 + 19];
                if (tmax < TS) c_acc += bt[tmax * 400 + j20 + lane];   // diag p==i
            }
            if (lane == 0) MB_ARRIVE(mb0 + r * 16 + 8);
        }
    }

    // ---------------- Epilogue ----------------
    if (wid == 22 && lane < 20) csts[lane] = c_acc;
    if (wid < 20) {
        float rv = reg1 + reg2;
#pragma unroll
        for (int o = 16; o > 0; o >>= 1) rv += __shfl_down_sync(0xffffffffu, rv, o);
        if (lane == 0) sredr[wid] = rv;
    }
    if (wid == 21) {
        double pv = (double)pair;
#pragma unroll
        for (int o = 16; o > 0; o >>= 1) pv += __shfl_down_sync(0xffffffffu, pv, o);
        if (lane == 0) g_res[i][1] = pv;
    }
    __syncthreads();

    if (wid < 20) bufs[lane * 21 + wid] = acc + csts[wid] + wsrow[wid];  // lgbuf[b*21+j]
    __syncthreads();

    if (tid < 32) {       // lse per b, minus single
        const float* row = &bufs[tid * 21];
        float m = row[0];
#pragma unroll
        for (int j = 1; j < A_; j++) m = fmaxf(m, row[j]);
        float se = 0.f;
#pragma unroll
        for (int j = 0; j < A_; j++) se += __expf(row[j] - m);
        float lse = m + __logf(se);
        double val = (double)lse - (double)wsrow[xi[tid]];
#pragma unroll
        for (int o = 16; o > 0; o >>= 1) val += __shfl_down_sync(0xffffffffu, val, o);
        if (tid == 0) g_res[i][0] = val;
    } else if (tid < 64) {   // reg sum over 20 warps
        double rv = (lane < 20) ? (double)sredr[lane] : 0.0;
#pragma unroll
        for (int o = 16; o > 0; o >>= 1) rv += __shfl_down_sync(0xffffffffu, rv, o);
        if (lane == 0) g_res[i][2] = rv;
    }
    __syncthreads();

    // ---------------- Fused deterministic final reduction (last CTA) ----------------
    if (tid == 0) {
        __threadfence();
        *amLast = (atomicAdd(&g_bcount, 1u) == (unsigned)(gridDim.x - 1)) ? 1 : 0;
    }
    __syncthreads();
    if (!*amLast) return;
    __threadfence();

    double LS = 0.0, PA = 0.0, RP = 0.0, RS = 0.0;
    if (tid < L_) { LS = g_res[tid][0]; PA = g_res[tid][1]; RP = g_res[tid][2]; }
    for (int n = tid; n < L_ * A_; n += NTHR) {
        float w = ws[n];
        RS += (double)fabsf(w) + (double)w * (double)w;
    }
    double* dred = reinterpret_cast<double*>(smem_raw + 4096);
#pragma unroll
    for (int o = 16; o > 0; o >>= 1) {
        LS += __shfl_down_sync(0xffffffffu, LS, o);
        PA += __shfl_down_sync(0xffffffffu, PA, o);
        RP += __shfl_down_sync(0xffffffffu, RP, o);
        RS += __shfl_down_sync(0xffffffffu, RS, o);
    }
    if (lane == 0) {
        dred[wid] = LS; dred[32 + wid] = PA; dred[64 + wid] = RP; dred[96 + wid] = RS;
    }
    __syncthreads();
    if (tid == 0) {
        double ls = 0, pa = 0, rp = 0, rs = 0;
        for (int w = 0; w < 23; w++) {
            ls += dred[w]; pa += dred[32 + w]; rp += dred[64 + w]; rs += dred[96 + w];
        }
        // LAMBDA_SINGLE = 1.0, LAMBDA_PAIR = 0.2*(L-1) = 51.0
        out[0] = (float)((ls - pa) / (double)B_ + 1.0 * rs + 51.0 * rp);
        g_bcount = 0;   // self-reset for graph replay
    }
}

extern "C" void kernel_launch(void* const* d_in, const int* in_sizes, int n_in,
                              void* d_out, int out_size) {
    (void)in_sizes; (void)n_in; (void)out_size;
    const int*   x  = (const int*)d_in[0];
    const float* ws = (const float*)d_in[1];
    const float* wp = (const float*)d_in[2];
    float* out = (float*)d_out;

    cudaFuncSetAttribute(mrf_kernel, cudaFuncAttributeMaxDynamicSharedMemorySize, SMEM_BYTES);
    mrf_kernel<<<L_, NTHR, SMEM_BYTES>>>(x, ws, wp, out);
}

// round 7
// speedup vs baseline: 1.4783x; 1.1812x over previous
#include <cuda_runtime.h>
#include <math.h>
#include <stdint.h>

#define B_ 32
#define L_ 256
#define A_ 20
#define NTHR 736            // 20 consumer warps + producer + pair + const
#define TS 16               // tiles per stage
#define RING 3
#define NSTAGE 16           // 256 tiles / 16
#define STAGE_F 6400
#define STAGE_BYTES 25600

__device__ double g_res[L_][3];          // per-i {lse_sum, pair_sum, reg_sum}
__device__ unsigned int g_bcount = 0;    // reset by last block each launch

// smem layout (bytes):
//   0     .. 76800  ring data (3 x 25600), row-major tiles
//   76800 .. 84992  xpk uint32[16][32][4]: bytes 4*x[b][p], p = sidx*16+w*4..+3
//   84992 .. 85120  xi[32]
//   85120 .. 85200  wsrow[20]
//   85200 .. 85280  csts[20]
//   85280 .. 85360  sredr[20]
//   85360 .. 85408  mbarriers per r (stride 16): full +0, empty +8
//   85408 .. 85412  amLast
// epilogue reuse: lgbuf f32[32*21] @f0, dred double[4*32] @byte 4096
#define SMEM_BYTES 85424
#define MB_OFF 85360

__device__ __forceinline__ uint32_t smem_u32(const void* p) {
    uint32_t a;
    asm("{ .reg .u64 t; cvta.to.shared.u64 t, %1; cvt.u32.u64 %0, t; }" : "=r"(a) : "l"(p));
    return a;
}
#define MB_INIT(addr, cnt) \
    asm volatile("mbarrier.init.shared.b64 [%0], %1;" :: "r"(addr), "r"(cnt) : "memory")
#define MB_EXPECT_TX(addr, bytes) \
    asm volatile("mbarrier.arrive.expect_tx.shared.b64 _, [%0], %1;" :: "r"(addr), "r"(bytes) : "memory")
#define MB_ARRIVE(addr) \
    asm volatile("mbarrier.arrive.shared.b64 _, [%0];" :: "r"(addr) : "memory")

__device__ __forceinline__ void mb_wait_acq(uint32_t mbar, uint32_t parity) {
    asm volatile(
        "{\n\t.reg .pred P;\n\t"
        "WL_%=:\n\t"
        "mbarrier.try_wait.parity.acquire.cta.shared::cta.b64 P, [%0], %1, 0x989680;\n\t"
        "@P bra.uni WD_%=;\n\t"
        "bra.uni WL_%=;\n\t"
        "WD_%=:\n\t}"
        :: "r"(mbar), "r"(parity) : "memory");
}
__device__ __forceinline__ void mb_wait_rlx(uint32_t mbar, uint32_t parity) {
    asm volatile(
        "{\n\t.reg .pred P;\n\t"
        "WL_%=:\n\t"
        "mbarrier.try_wait.parity.relaxed.cta.shared::cta.b64 P, [%0], %1, 0x989680;\n\t"
        "@P bra.uni WD_%=;\n\t"
        "bra.uni WL_%=;\n\t"
        "WD_%=:\n\t}"
        :: "r"(mbar), "r"(parity) : "memory");
}
__device__ __forceinline__ void bulk_g2s(uint32_t dst, const void* src,
                                         uint32_t bytes, uint32_t mbar) {
    asm volatile(
        "cp.async.bulk.shared::cta.global.mbarrier::complete_tx::bytes [%0], [%1], %2, [%3];"
        :: "r"(dst), "l"(src), "r"(bytes), "r"(mbar) : "memory");
}

__global__ __launch_bounds__(NTHR, 2) void mrf_kernel(const int* __restrict__ x,
                                                      const float* __restrict__ ws,
                                                      const float* __restrict__ wp,
                                                      float* __restrict__ out) {
    extern __shared__ char smem_raw[];
    float*        bufs  = reinterpret_cast<float*>(smem_raw);
    uint32_t*     xpk   = reinterpret_cast<uint32_t*>(smem_raw + 76800);
    int*          xi    = reinterpret_cast<int*>(smem_raw + 84992);
    float*        wsrow = reinterpret_cast<float*>(smem_raw + 85120);
    float*        csts  = reinterpret_cast<float*>(smem_raw + 85200);
    float*        sredr = reinterpret_cast<float*>(smem_raw + 85280);
    int*          amLast= reinterpret_cast<int*>(smem_raw + 85408);
    const uint32_t mb0  = smem_u32(smem_raw + MB_OFF);
    const uint32_t bufa = smem_u32(smem_raw);

    const int i    = blockIdx.x;
    const int tid  = threadIdx.x;
    const int wid  = tid >> 5;
    const int lane = tid & 31;

    // full: tx-based (count 1). empty: 22 arrivals (20 consumers + pair + const).
    if (tid == 0) {
        for (int r = 0; r < RING; r++) {
            MB_INIT(mb0 + r * 16, 1);
            MB_INIT(mb0 + r * 16 + 8, 22);
        }
    }

    // Pack x transpose, pre-scaled by 4: xpk[sidx*128 + lane*4 + w] holds bytes
    // 4*x[b=lane][p = sidx*16 + 4w .. +3]
    const int4* x4 = reinterpret_cast<const int4*>(x);
    for (int n = tid; n < 2048; n += NTHR) {
        int sidx = n >> 7, rem = n & 127;
        int b = rem >> 2, w = rem & 3;
        int4 q = x4[b * 64 + sidx * 4 + w];
        xpk[n] = (uint32_t)(q.x << 2) | ((uint32_t)(q.y << 2) << 8) |
                 ((uint32_t)(q.z << 2) << 16) | ((uint32_t)(q.w << 2) << 24);
    }
    if (tid < B_) xi[tid] = x[tid * L_ + i];
    if (tid >= 32 && tid < 52) wsrow[tid - 32] = ws[i * A_ + (tid - 32)];
    asm volatile("fence.proxy.async.shared::cta;" ::: "memory");
    __syncthreads();

    float acc = 0.f, pair = 0.f, c_acc = 0.f, reg1 = 0.f, reg2 = 0.f;

    if (wid < 20) {
        // ---- Consumers: warp = j, lane = b; gather p>i + reg pass ----
        const char* btj0 = smem_raw + wid * 80;   // + r*STAGE_BYTES later
        const uint4* xpk4 = reinterpret_cast<const uint4*>(xpk);
        const float4* b4all = reinterpret_cast<const float4*>(smem_raw);
        const float2* b2all = reinterpret_cast<const float2*>(smem_raw);
        int r = 0, ph = 0;
        for (int sidx = 0; sidx < NSTAGE; sidx++) {
            mb_wait_acq(mb0 + r * 16, ph);

            // reg pass: 10 floats/lane (2 x LDS.128 + 1 x LDS.64)
            {
                float4 q1 = b4all[r * 1600 + tid];
                float4 q2 = b4all[r * 1600 + 640 + tid];
                float2 t2 = b2all[r * 3200 + 2560 + tid];
                reg1 += fabsf(q1.x); reg2 = fmaf(q1.x, q1.x, reg2);
                reg1 += fabsf(q1.y); reg2 = fmaf(q1.y, q1.y, reg2);
                reg1 += fabsf(q1.z); reg2 = fmaf(q1.z, q1.z, reg2);
                reg1 += fabsf(q1.w); reg2 = fmaf(q1.w, q1.w, reg2);
                reg1 += fabsf(q2.x); reg2 = fmaf(q2.x, q2.x, reg2);
                reg1 += fabsf(q2.y); reg2 = fmaf(q2.y, q2.y, reg2);
                reg1 += fabsf(q2.z); reg2 = fmaf(q2.z, q2.z, reg2);
                reg1 += fabsf(q2.w); reg2 = fmaf(q2.w, q2.w, reg2);
                reg1 += fabsf(t2.x); reg2 = fmaf(t2.x, t2.x, reg2);
                reg1 += fabsf(t2.y); reg2 = fmaf(t2.y, t2.y, reg2);
            }

            const int pbase = sidx * TS;
            if (pbase + TS - 1 > i) {
                const char* btj = btj0 + r * STAGE_BYTES;
                const uint4 u = xpk4[sidx * 32 + lane];
                const uint32_t wv[4] = {u.x, u.y, u.z, u.w};
                if (pbase > i) {          // ABOVE: all 16 tiles
#pragma unroll
                    for (int k = 0; k < TS; k++) {
                        uint32_t e4 = __byte_perm(wv[k >> 2], 0, 0x4440 | (k & 3));
                        acc += *reinterpret_cast<const float*>(btj + k * 1600 + e4);
                    }
                } else {                  // MIXED
#pragma unroll
                    for (int k = 0; k < TS; k++) {
                        uint32_t e4 = __byte_perm(wv[k >> 2], 0, 0x4440 | (k & 3));
                        if (pbase + k > i)
                            acc += *reinterpret_cast<const float*>(btj + k * 1600 + e4);
                    }
                }
            }
            if (lane == 0) MB_ARRIVE(mb0 + r * 16 + 8);
            if (++r == RING) { r = 0; ph ^= 1; }
        }
    } else if (wid == 20) {
        // ---- Producer (lane 0) ----
        if (lane == 0) {
            const char* src = reinterpret_cast<const char*>(wp) + (size_t)i * 409600;
            int r = 0, wr = 0, wph = 0;
            for (int sidx = 0; sidx < NSTAGE; sidx++) {
                if (sidx >= RING) {
                    mb_wait_rlx(mb0 + wr * 16 + 8, wph);
                    if (++wr == RING) { wr = 0; wph ^= 1; }
                }
                MB_EXPECT_TX(mb0 + r * 16, STAGE_BYTES);
                bulk_g2s(bufa + r * STAGE_BYTES, src + (size_t)sidx * STAGE_BYTES,
                         STAGE_BYTES, mb0 + r * 16);
                if (++r == RING) r = 0;
            }
        }
    } else if (wid == 21) {
        // ---- Pair warp: lane = b, all p ----
        const char* bt0 = smem_raw + xi[lane] * 80;
        const uint4* xpk4 = reinterpret_cast<const uint4*>(xpk);
        int r = 0, ph = 0;
        for (int sidx = 0; sidx < NSTAGE; sidx++) {
            mb_wait_acq(mb0 + r * 16, ph);
            const char* bt = bt0 + r * STAGE_BYTES;
            const uint4 u = xpk4[sidx * 32 + lane];
            const uint32_t wv[4] = {u.x, u.y, u.z, u.w};
#pragma unroll
            for (int k = 0; k < TS; k++) {
                uint32_t e4 = __byte_perm(wv[k >> 2], 0, 0x4440 | (k & 3));
                pair += *reinterpret_cast<const float*>(bt + k * 1600 + e4);
            }
            if (lane == 0) MB_ARRIVE(mb0 + r * 16 + 8);
            if (++r == RING) { r = 0; ph ^= 1; }
        }
    } else {
        // ---- Const warp: lanes 0..19, j = lane ----
        const int j20 = lane * 20;
        int r = 0, ph = 0;
        for (int sidx = 0; sidx < NSTAGE; sidx++) {
            mb_wait_acq(mb0 + r * 16, ph);
            const int pbase = sidx * TS;
            if (lane < 20 && pbase <= i) {
                const float* bt = bufs + r * STAGE_F;
                int tmax = i - pbase;              // t < tmax  <=>  p < i
                int lim = tmax < TS ? tmax : TS;
                for (int t = 0; t < lim; t++) c_acc += bt[t * 400 + j20 + 19];
                if (tmax < TS) c_acc += bt[tmax * 400 + j20 + lane];   // diag p==i
            }
            if (lane == 0) MB_ARRIVE(mb0 + r * 16 + 8);
            if (++r == RING) { r = 0; ph ^= 1; }
        }
    }

    // ---------------- Epilogue ----------------
    if (wid == 22 && lane < 20) csts[lane] = c_acc;
    if (wid < 20) {
        float rv = reg1 + reg2;
#pragma unroll
        for (int o = 16; o > 0; o >>= 1) rv += __shfl_down_sync(0xffffffffu, rv, o);
        if (lane == 0) sredr[wid] = rv;
    }
    if (wid == 21) {
        double pv = (double)pair;
#pragma unroll
        for (int o = 16; o > 0; o >>= 1) pv += __shfl_down_sync(0xffffffffu, pv, o);
        if (lane == 0) g_res[i][1] = pv;
    }
    __syncthreads();

    if (wid < 20) bufs[lane * 21 + wid] = acc + csts[wid] + wsrow[wid];  // lgbuf[b*21+j]
    __syncthreads();

    if (tid < 32) {       // lse per b, minus single
        const float* row = &bufs[tid * 21];
        float m = row[0];
#pragma unroll
        for (int j = 1; j < A_; j++) m = fmaxf(m, row[j]);
        float se = 0.f;
#pragma unroll
        for (int j = 0; j < A_; j++) se += __expf(row[j] - m);
        float lse = m + __logf(se);
        double val = (double)lse - (double)wsrow[xi[tid]];
#pragma unroll
        for (int o = 16; o > 0; o >>= 1) val += __shfl_down_sync(0xffffffffu, val, o);
        if (tid == 0) g_res[i][0] = val;
    } else if (tid < 64) {   // reg sum over 20 warps
        double rv = (lane < 20) ? (double)sredr[lane] : 0.0;
#pragma unroll
        for (int o = 16; o > 0; o >>= 1) rv += __shfl_down_sync(0xffffffffu, rv, o);
        if (lane == 0) g_res[i][2] = rv;
    }
    __syncthreads();

    // ---------------- Fused deterministic final reduction (last CTA) ----------------
    if (tid == 0) {
        __threadfence();
        *amLast = (atomicAdd(&g_bcount, 1u) == (unsigned)(gridDim.x - 1)) ? 1 : 0;
    }
    __syncthreads();
    if (!*amLast) return;
    __threadfence();

    double LS = 0.0, PA = 0.0, RP = 0.0, RS = 0.0;
    if (tid < L_) { LS = g_res[tid][0]; PA = g_res[tid][1]; RP = g_res[tid][2]; }
    for (int n = tid; n < L_ * A_; n += NTHR) {
        float w = ws[n];
        RS += (double)fabsf(w) + (double)w * (double)w;
    }
    double* dred = reinterpret_cast<double*>(smem_raw + 4096);
#pragma unroll
    for (int o = 16; o > 0; o >>= 1) {
        LS += __shfl_down_sync(0xffffffffu, LS, o);
        PA += __shfl_down_sync(0xffffffffu, PA, o);
        RP += __shfl_down_sync(0xffffffffu, RP, o);
        RS += __shfl_down_sync(0xffffffffu, RS, o);
    }
    if (lane == 0) {
        dred[wid] = LS; dred[32 + wid] = PA; dred[64 + wid] = RP; dred[96 + wid] = RS;
    }
    __syncthreads();
    if (tid == 0) {
        double ls = 0, pa = 0, rp = 0, rs = 0;
        for (int w = 0; w < 23; w++) {
            ls += dred[w]; pa += dred[32 + w]; rp += dred[64 + w]; rs += dred[96 + w];
        }
        // LAMBDA_SINGLE = 1.0, LAMBDA_PAIR = 0.2*(L-1) = 51.0
        out[0] = (float)((ls - pa) / (double)B_ + 1.0 * rs + 51.0 * rp);
        g_bcount = 0;   // self-reset for graph replay
    }
}

extern "C" void kernel_launch(void* const* d_in, const int* in_sizes, int n_in,
                              void* d_out, int out_size) {
    (void)in_sizes; (void)n_in; (void)out_size;
    const int*   x  = (const int*)d_in[0];
    const float* ws = (const float*)d_in[1];
    const float* wp = (const float*)d_in[2];
    float* out = (float*)d_out;

    cudaFuncSetAttribute(mrf_kernel, cudaFuncAttributeMaxDynamicSharedMemorySize, SMEM_BYTES);
    mrf_kernel<<<L_, NTHR, SMEM_BYTES>>>(x, ws, wp, out);
}